// round 1
// baseline (speedup 1.0000x reference)
#include <cuda_runtime.h>
#include <math_constants.h>

#define NPTS 4096
#define DDATA 1024
#define DLAT 64
#define NEDGE (NPTS - 1)

// ---- scratch (no allocations allowed: device globals) ----
static __device__ float g_ddist[(size_t)NPTS * NPTS];   // raw data distances
static __device__ float g_ldist[(size_t)NPTS * NPTS];   // raw latent distances
static __device__ float g_sqd[NPTS];
static __device__ float g_sql[NPTS];
static __device__ float g_ae[NPTS];
static __device__ int   g_edges[2][NEDGE * 2];
static __device__ unsigned g_dmax_bits;
static __device__ float g_topo;

__global__ void init_kernel() { g_dmax_bits = 0u; }

// ---- AE loss + squared norms of y_true (one block per row) ----
__global__ void __launch_bounds__(256) ae_sq_kernel(
    const float* __restrict__ yt, const float* __restrict__ yp) {
    int row = blockIdx.x, tid = threadIdx.x;
    float4 a = ((const float4*)(yt + (size_t)row * DDATA))[tid];
    float4 b = ((const float4*)(yp + (size_t)row * DDATA))[tid];
    float dx = a.x - b.x, dy = a.y - b.y, dz = a.z - b.z, dw = a.w - b.w;
    float ae = dx * dx + dy * dy + dz * dz + dw * dw;
    float sq = a.x * a.x + a.y * a.y + a.z * a.z + a.w * a.w;
#pragma unroll
    for (int off = 16; off; off >>= 1) {
        ae += __shfl_down_sync(0xffffffffu, ae, off);
        sq += __shfl_down_sync(0xffffffffu, sq, off);
    }
    __shared__ float sae[8], ssq[8];
    if ((tid & 31) == 0) { sae[tid >> 5] = ae; ssq[tid >> 5] = sq; }
    __syncthreads();
    if (tid < 8) {
        ae = sae[tid]; sq = ssq[tid];
#pragma unroll
        for (int off = 4; off; off >>= 1) {
            ae += __shfl_down_sync(0xffu, ae, off);
            sq += __shfl_down_sync(0xffu, sq, off);
        }
        if (tid == 0) { g_ae[row] = ae * (1.0f / DDATA); g_sqd[row] = sq; }
    }
}

// ---- squared norms of latent rows (one warp per row) ----
__global__ void __launch_bounds__(32) sq_lat_kernel(const float* __restrict__ lat) {
    int row = blockIdx.x, tid = threadIdx.x;
    float2 v = ((const float2*)(lat + (size_t)row * DLAT))[tid];
    float s = v.x * v.x + v.y * v.y;
#pragma unroll
    for (int off = 16; off; off >>= 1) s += __shfl_down_sync(0xffffffffu, s, off);
    if (tid == 0) g_sql[row] = s;
}

// ---- symmetric gram -> Euclidean distance matrix ----
// 128x128 tile per block, 256 threads, 8x8 per thread, BK=8.
// Only bi<=bj computed; mirror written. which==0 => data (track max).
__global__ void __launch_bounds__(256) gram_kernel(
    const float* __restrict__ X, int K, int which) {
    int bj = blockIdx.x, bi = blockIdx.y;
    if (bi > bj) return;
    const float* __restrict__ sq = (which == 0) ? g_sqd : g_sql;
    float* __restrict__ D = (which == 0) ? g_ddist : g_ldist;

    __shared__ float As[8][128], Bs[8][128];
    int tid = threadIdx.x;
    int tx = tid & 15, ty = tid >> 4;
    float acc[8][8];
#pragma unroll
    for (int m = 0; m < 8; m++)
#pragma unroll
        for (int n = 0; n < 8; n++) acc[m][n] = 0.f;

    int lr = tid >> 1;              // 0..127
    int lk = (tid & 1) << 2;        // 0 or 4
    const float* Ap = X + (size_t)(bi * 128 + lr) * K + lk;
    const float* Bp = X + (size_t)(bj * 128 + lr) * K + lk;

    for (int k0 = 0; k0 < K; k0 += 8) {
        float4 a = *(const float4*)(Ap + k0);
        float4 b = *(const float4*)(Bp + k0);
        __syncthreads();
        As[lk + 0][lr] = a.x; As[lk + 1][lr] = a.y;
        As[lk + 2][lr] = a.z; As[lk + 3][lr] = a.w;
        Bs[lk + 0][lr] = b.x; Bs[lk + 1][lr] = b.y;
        Bs[lk + 2][lr] = b.z; Bs[lk + 3][lr] = b.w;
        __syncthreads();
#pragma unroll
        for (int kk = 0; kk < 8; kk++) {
            float ar[8], br[8];
            *(float4*)(ar)     = *(const float4*)(&As[kk][ty * 8]);
            *(float4*)(ar + 4) = *(const float4*)(&As[kk][ty * 8 + 4]);
            *(float4*)(br)     = *(const float4*)(&Bs[kk][tx * 8]);
            *(float4*)(br + 4) = *(const float4*)(&Bs[kk][tx * 8 + 4]);
#pragma unroll
            for (int m = 0; m < 8; m++)
#pragma unroll
                for (int n = 0; n < 8; n++) acc[m][n] += ar[m] * br[n];
        }
    }

    float sqa[8], sqb[8];
#pragma unroll
    for (int m = 0; m < 8; m++) sqa[m] = sq[bi * 128 + ty * 8 + m];
#pragma unroll
    for (int n = 0; n < 8; n++) sqb[n] = sq[bj * 128 + tx * 8 + n];

    float lmax = 0.f;
#pragma unroll
    for (int m = 0; m < 8; m++) {
        int gi = bi * 128 + ty * 8 + m;
#pragma unroll
        for (int n = 0; n < 8; n++) {
            int gj = bj * 128 + tx * 8 + n;
            float d2 = sqa[m] + sqb[n] - 2.0f * acc[m][n];
            float d = (d2 > 0.f) ? sqrtf(d2) : 0.f;
            D[(size_t)gi * NPTS + gj] = d;
            if (bi != bj) D[(size_t)gj * NPTS + gi] = d;
            lmax = fmaxf(lmax, d);
        }
    }

    if (which == 0) {
#pragma unroll
        for (int off = 16; off; off >>= 1)
            lmax = fmaxf(lmax, __shfl_down_sync(0xffffffffu, lmax, off));
        __shared__ float smax[8];
        if ((tid & 31) == 0) smax[tid >> 5] = lmax;
        __syncthreads();
        if (tid == 0) {
            float m = smax[0];
#pragma unroll
            for (int w = 1; w < 8; w++) m = fmaxf(m, smax[w]);
            atomicMax(&g_dmax_bits, __float_as_uint(m));
        }
    }
}

// ---- Prim's MST, one block per matrix (block 0: data, block 1: latent) ----
// min_dist/min_src live in registers (4 per thread). In-tree nodes are marked
// with -1.f (distances >= 0, so "dj < val" can never un-mark them).
// Tie-break: strict < on value, then lowest global index (matches jnp.argmin).
__global__ void __launch_bounds__(1024, 1) mst_kernel() {
    const float* __restrict__ dist = (blockIdx.x == 0) ? g_ddist : g_ldist;
    int* __restrict__ edges = g_edges[blockIdx.x];

    __shared__ float s_rv[32];
    __shared__ int s_ri[32];
    __shared__ int s_sel;

    int tid = threadIdx.x;
    int lane = tid & 31, w = tid >> 5;

    float val[4]; int src[4];
#pragma unroll
    for (int c = 0; c < 4; c++) { val[c] = dist[tid + (c << 10)]; src[c] = 0; }
    if (tid == 0) val[0] = -1.f;   // node 0 is in the tree

    for (int step = 0; step < NEDGE; step++) {
        // local argmin over this thread's 4 slots
        float bv = CUDART_INF_F; int bk = 0x7fffffff;
#pragma unroll
        for (int c = 0; c < 4; c++) {
            float v = val[c];
            float vv = (v < 0.f) ? CUDART_INF_F : v;
            if (vv < bv) { bv = vv; bk = tid + (c << 10); }
        }
        // warp argmin
#pragma unroll
        for (int off = 16; off; off >>= 1) {
            float ov = __shfl_down_sync(0xffffffffu, bv, off);
            int   ok = __shfl_down_sync(0xffffffffu, bk, off);
            if (ov < bv || (ov == bv && ok < bk)) { bv = ov; bk = ok; }
        }
        if (lane == 0) { s_rv[w] = bv; s_ri[w] = bk; }
        __syncthreads();
        if (w == 0) {
            bv = s_rv[lane]; bk = s_ri[lane];
#pragma unroll
            for (int off = 16; off; off >>= 1) {
                float ov = __shfl_down_sync(0xffffffffu, bv, off);
                int   ok = __shfl_down_sync(0xffffffffu, bk, off);
                if (ov < bv || (ov == bv && ok < bk)) { bv = ov; bk = ok; }
            }
            if (lane == 0) s_sel = bk;
        }
        __syncthreads();
        int j = s_sel;
        if ((j & 1023) == tid) {           // owning thread emits the edge
            int c = j >> 10;
            edges[2 * step]     = src[c];
            edges[2 * step + 1] = j;
            val[c] = -1.f;                 // add j to tree
        }
        // relax with row j (coalesced, read exactly once over the run)
        const float* row = dist + (size_t)j * NPTS;
        float d0 = row[tid];
        float d1 = row[tid + 1024];
        float d2 = row[tid + 2048];
        float d3 = row[tid + 3072];
        if (d0 < val[0]) { val[0] = d0; src[0] = j; }
        if (d1 < val[1]) { val[1] = d1; src[1] = j; }
        if (d2 < val[2]) { val[2] = d2; src[2] = j; }
        if (d3 < val[3]) { val[3] = d3; src[3] = j; }
    }
}

// ---- gather MST edges, compute topo loss ----
__global__ void __launch_bounds__(1024) topo_kernel(const float* __restrict__ lnorm) {
    int tid = threadIdx.x;
    float invmax = 1.0f / __uint_as_float(g_dmax_bits);
    float invln = 1.0f / lnorm[0];
    float sd = 0.f, sl = 0.f;
    for (int e = tid; e < NEDGE; e += 1024) {
        int u = g_edges[0][2 * e], v = g_edges[0][2 * e + 1];
        size_t o = (size_t)u * NPTS + v;
        float t = g_ddist[o] * invmax - g_ldist[o] * invln;
        sd += t * t;
        u = g_edges[1][2 * e]; v = g_edges[1][2 * e + 1];
        o = (size_t)u * NPTS + v;
        t = g_ddist[o] * invmax - g_ldist[o] * invln;
        sl += t * t;
    }
#pragma unroll
    for (int off = 16; off; off >>= 1) {
        sd += __shfl_down_sync(0xffffffffu, sd, off);
        sl += __shfl_down_sync(0xffffffffu, sl, off);
    }
    __shared__ float ssd[32], ssl[32];
    if ((tid & 31) == 0) { ssd[tid >> 5] = sd; ssl[tid >> 5] = sl; }
    __syncthreads();
    if (tid < 32) {
        sd = ssd[tid]; sl = ssl[tid];
#pragma unroll
        for (int off = 16; off; off >>= 1) {
            sd += __shfl_down_sync(0xffffffffu, sd, off);
            sl += __shfl_down_sync(0xffffffffu, sl, off);
        }
        if (tid == 0) g_topo = (sd + sl) * (1.0f / NEDGE);
    }
}

__global__ void final_kernel(float* __restrict__ out) {
    int i = blockIdx.x * blockDim.x + threadIdx.x;
    if (i < NPTS) out[i] = g_ae[i] + 0.5f * g_topo;
}

extern "C" void kernel_launch(void* const* d_in, const int* in_sizes, int n_in,
                              void* d_out, int out_size) {
    const float* y_true      = (const float*)d_in[0];
    const float* latent      = (const float*)d_in[1];
    const float* y_pred      = (const float*)d_in[2];
    const float* latent_norm = (const float*)d_in[3];
    float* out = (float*)d_out;

    init_kernel<<<1, 1>>>();
    ae_sq_kernel<<<NPTS, 256>>>(y_true, y_pred);
    sq_lat_kernel<<<NPTS, 32>>>(latent);
    dim3 grid(32, 32);
    gram_kernel<<<grid, 256>>>(y_true, DDATA, 0);
    gram_kernel<<<grid, 256>>>(latent, DLAT, 1);
    mst_kernel<<<2, 1024>>>();
    topo_kernel<<<1, 1024>>>(latent_norm);
    final_kernel<<<16, 256>>>(out);
}

// round 2
// speedup vs baseline: 6.7912x; 6.7912x over previous
#include <cuda_runtime.h>
#include <math_constants.h>

#define NPTS 4096
#define DDATA 1024
#define DLAT 64
#define NEDGE (NPTS - 1)
#define ROUNDS 12

// ---- scratch (no allocations allowed: device globals) ----
static __device__ float g_ddist[(size_t)NPTS * NPTS];   // raw data distances
static __device__ float g_ldist[(size_t)NPTS * NPTS];   // raw latent distances
static __device__ float g_sqd[NPTS];
static __device__ float g_sql[NPTS];
static __device__ float g_ae[NPTS];
static __device__ int   g_edges[2][NEDGE * 2];
static __device__ int   g_ecnt[2];
static __device__ int   g_done[2];
static __device__ int   g_comp[2][NPTS];
static __device__ int   g_parent[2][NPTS];
static __device__ unsigned long long g_nbest[2][NPTS];
static __device__ unsigned g_dmax_bits;
static __device__ float g_topo;

__global__ void init_kernel() {
    int i = blockIdx.x * blockDim.x + threadIdx.x;
    if (i < NPTS) { g_comp[0][i] = i; g_comp[1][i] = i; }
    if (i == 0) {
        g_dmax_bits = 0u;
        g_ecnt[0] = 0; g_ecnt[1] = 0;
        g_done[0] = 0; g_done[1] = 0;
    }
}

// ---- AE loss + squared norms of y_true (one block per row) ----
__global__ void __launch_bounds__(256) ae_sq_kernel(
    const float* __restrict__ yt, const float* __restrict__ yp) {
    int row = blockIdx.x, tid = threadIdx.x;
    float4 a = ((const float4*)(yt + (size_t)row * DDATA))[tid];
    float4 b = ((const float4*)(yp + (size_t)row * DDATA))[tid];
    float dx = a.x - b.x, dy = a.y - b.y, dz = a.z - b.z, dw = a.w - b.w;
    float ae = dx * dx + dy * dy + dz * dz + dw * dw;
    float sq = a.x * a.x + a.y * a.y + a.z * a.z + a.w * a.w;
#pragma unroll
    for (int off = 16; off; off >>= 1) {
        ae += __shfl_down_sync(0xffffffffu, ae, off);
        sq += __shfl_down_sync(0xffffffffu, sq, off);
    }
    __shared__ float sae[8], ssq[8];
    if ((tid & 31) == 0) { sae[tid >> 5] = ae; ssq[tid >> 5] = sq; }
    __syncthreads();
    if (tid < 8) {
        ae = sae[tid]; sq = ssq[tid];
#pragma unroll
        for (int off = 4; off; off >>= 1) {
            ae += __shfl_down_sync(0xffu, ae, off);
            sq += __shfl_down_sync(0xffu, sq, off);
        }
        if (tid == 0) { g_ae[row] = ae * (1.0f / DDATA); g_sqd[row] = sq; }
    }
}

// ---- squared norms of latent rows (one warp per row) ----
__global__ void __launch_bounds__(32) sq_lat_kernel(const float* __restrict__ lat) {
    int row = blockIdx.x, tid = threadIdx.x;
    float2 v = ((const float2*)(lat + (size_t)row * DLAT))[tid];
    float s = v.x * v.x + v.y * v.y;
#pragma unroll
    for (int off = 16; off; off >>= 1) s += __shfl_down_sync(0xffffffffu, s, off);
    if (tid == 0) g_sql[row] = s;
}

// ---- symmetric gram -> Euclidean distance matrix ----
__global__ void __launch_bounds__(256) gram_kernel(
    const float* __restrict__ X, int K, int which) {
    int bj = blockIdx.x, bi = blockIdx.y;
    if (bi > bj) return;
    const float* __restrict__ sq = (which == 0) ? g_sqd : g_sql;
    float* __restrict__ D = (which == 0) ? g_ddist : g_ldist;

    __shared__ float As[8][128], Bs[8][128];
    int tid = threadIdx.x;
    int tx = tid & 15, ty = tid >> 4;
    float acc[8][8];
#pragma unroll
    for (int m = 0; m < 8; m++)
#pragma unroll
        for (int n = 0; n < 8; n++) acc[m][n] = 0.f;

    int lr = tid >> 1;
    int lk = (tid & 1) << 2;
    const float* Ap = X + (size_t)(bi * 128 + lr) * K + lk;
    const float* Bp = X + (size_t)(bj * 128 + lr) * K + lk;

    for (int k0 = 0; k0 < K; k0 += 8) {
        float4 a = *(const float4*)(Ap + k0);
        float4 b = *(const float4*)(Bp + k0);
        __syncthreads();
        As[lk + 0][lr] = a.x; As[lk + 1][lr] = a.y;
        As[lk + 2][lr] = a.z; As[lk + 3][lr] = a.w;
        Bs[lk + 0][lr] = b.x; Bs[lk + 1][lr] = b.y;
        Bs[lk + 2][lr] = b.z; Bs[lk + 3][lr] = b.w;
        __syncthreads();
#pragma unroll
        for (int kk = 0; kk < 8; kk++) {
            float ar[8], br[8];
            *(float4*)(ar)     = *(const float4*)(&As[kk][ty * 8]);
            *(float4*)(ar + 4) = *(const float4*)(&As[kk][ty * 8 + 4]);
            *(float4*)(br)     = *(const float4*)(&Bs[kk][tx * 8]);
            *(float4*)(br + 4) = *(const float4*)(&Bs[kk][tx * 8 + 4]);
#pragma unroll
            for (int m = 0; m < 8; m++)
#pragma unroll
                for (int n = 0; n < 8; n++) acc[m][n] += ar[m] * br[n];
        }
    }

    float sqa[8], sqb[8];
#pragma unroll
    for (int m = 0; m < 8; m++) sqa[m] = sq[bi * 128 + ty * 8 + m];
#pragma unroll
    for (int n = 0; n < 8; n++) sqb[n] = sq[bj * 128 + tx * 8 + n];

    float lmax = 0.f;
#pragma unroll
    for (int m = 0; m < 8; m++) {
        int gi = bi * 128 + ty * 8 + m;
#pragma unroll
        for (int n = 0; n < 8; n++) {
            int gj = bj * 128 + tx * 8 + n;
            float d2 = sqa[m] + sqb[n] - 2.0f * acc[m][n];
            float d = (d2 > 0.f) ? sqrtf(d2) : 0.f;
            D[(size_t)gi * NPTS + gj] = d;
            if (bi != bj) D[(size_t)gj * NPTS + gi] = d;
            lmax = fmaxf(lmax, d);
        }
    }

    if (which == 0) {
#pragma unroll
        for (int off = 16; off; off >>= 1)
            lmax = fmaxf(lmax, __shfl_down_sync(0xffffffffu, lmax, off));
        __shared__ float smax[8];
        if ((tid & 31) == 0) smax[tid >> 5] = lmax;
        __syncthreads();
        if (tid == 0) {
            float m = smax[0];
#pragma unroll
            for (int w = 1; w < 8; w++) m = fmaxf(m, smax[w]);
            atomicMax(&g_dmax_bits, __float_as_uint(m));
        }
    }
}

// ---- Boruvka scan: per-node min outgoing edge (one warp per row) ----
// grid (512, 2): blockIdx.y = matrix, 8 rows per 256-thread block.
__global__ void __launch_bounds__(256) boruvka_scan() {
    int m = blockIdx.y;
    if (g_done[m]) return;
    const float* __restrict__ dist = (m == 0) ? g_ddist : g_ldist;
    const int* __restrict__ comp = g_comp[m];

    __shared__ __align__(16) int scomp[NPTS];
    for (int t = threadIdx.x; t < NPTS; t += 256) scomp[t] = comp[t];
    __syncthreads();

    int w = threadIdx.x >> 5, lane = threadIdx.x & 31;
    int row = blockIdx.x * 8 + w;
    int mycomp = scomp[row];
    const float4* __restrict__ rp = (const float4*)(dist + (size_t)row * NPTS);
    const int4* __restrict__ cp = (const int4*)scomp;

    unsigned bestv = 0xFFFFFFFFu;
    int bestj = 0;
#pragma unroll 8
    for (int k = 0; k < 32; k++) {
        int c4 = k * 32 + lane;
        float4 v = rp[c4];
        int4 cc = cp[c4];
        int col = c4 << 2;
        unsigned b;
        b = __float_as_uint(v.x); if (cc.x != mycomp && b < bestv) { bestv = b; bestj = col; }
        b = __float_as_uint(v.y); if (cc.y != mycomp && b < bestv) { bestv = b; bestj = col + 1; }
        b = __float_as_uint(v.z); if (cc.z != mycomp && b < bestv) { bestv = b; bestj = col + 2; }
        b = __float_as_uint(v.w); if (cc.w != mycomp && b < bestv) { bestv = b; bestj = col + 3; }
    }
    unsigned rv = __reduce_min_sync(0xffffffffu, bestv);
    unsigned rj = __reduce_min_sync(0xffffffffu,
                                    (bestv == rv) ? (unsigned)bestj : 0xFFFFFFFFu);
    if (lane == 0)
        g_nbest[m][row] = ((unsigned long long)rv << 24)
                        | ((unsigned long long)row << 12)
                        | (unsigned long long)rj;
}

// ---- Boruvka merge: per-comp best, hook, pointer-jump, relabel ----
// grid 2 blocks (one per matrix), 1024 threads.
__global__ void __launch_bounds__(1024) boruvka_merge() {
    int m = blockIdx.x;
    if (g_done[m]) return;
    __shared__ __align__(8) unsigned long long table[NPTS];  // 32 KB
    __shared__ int scnt;
    int tid = threadIdx.x;
    int* __restrict__ parent = g_parent[m];
    const int* __restrict__ comp = g_comp[m];

    for (int c = tid; c < NPTS; c += 1024) { table[c] = ~0ull; parent[c] = c; }
    if (tid == 0) scnt = 0;
    __syncthreads();

    // per-component best edge
    for (int n = tid; n < NPTS; n += 1024)
        atomicMin(&table[comp[n]], g_nbest[m][n]);
    __syncthreads();

    // hooking + edge emission (2-cycle break at smaller root)
    for (int c = tid; c < NPTS; c += 1024) {
        unsigned long long e = table[c];
        if (e != ~0ull) {
            int i = (int)((e >> 12) & 0xFFF);
            int j = (int)(e & 0xFFF);
            int t = comp[j];
            unsigned long long et = table[t];
            int i2 = (int)((et >> 12) & 0xFFF);
            int j2 = (int)(et & 0xFFF);
            bool mutual = (i2 == j) && (j2 == i);
            if (!mutual || c < t) {
                int pos = atomicAdd(&g_ecnt[m], 1);
                g_edges[m][2 * pos]     = i;
                g_edges[m][2 * pos + 1] = j;
            }
            parent[c] = (mutual && c < t) ? c : t;
        }
    }
    __syncthreads();

    // pointer jumping (12 iterations guarantees full collapse)
    for (int it = 0; it < 12; it++) {
        for (int c = tid; c < NPTS; c += 1024) {
            int p = parent[c];
            parent[c] = parent[p];
        }
        __syncthreads();
    }

    // relabel + distinct-root count (reuse table as mark array)
    int* mark = (int*)table;
    for (int c = tid; c < NPTS; c += 1024) mark[c] = 0;
    __syncthreads();
    for (int n = tid; n < NPTS; n += 1024) {
        int r = parent[comp[n]];
        g_comp[m][n] = r;
        mark[r] = 1;
    }
    __syncthreads();
    int cnt = 0;
    for (int c = tid; c < NPTS; c += 1024) cnt += mark[c];
#pragma unroll
    for (int off = 16; off; off >>= 1) cnt += __shfl_down_sync(0xffffffffu, cnt, off);
    if ((tid & 31) == 0) atomicAdd(&scnt, cnt);
    __syncthreads();
    if (tid == 0 && scnt == 1) g_done[m] = 1;
}

// ---- gather MST edges, compute topo loss ----
__global__ void __launch_bounds__(1024) topo_kernel(const float* __restrict__ lnorm) {
    int tid = threadIdx.x;
    float invmax = 1.0f / __uint_as_float(g_dmax_bits);
    float invln = 1.0f / lnorm[0];
    float sd = 0.f, sl = 0.f;
    for (int e = tid; e < NEDGE; e += 1024) {
        int u = g_edges[0][2 * e], v = g_edges[0][2 * e + 1];
        size_t o = (size_t)u * NPTS + v;
        float t = g_ddist[o] * invmax - g_ldist[o] * invln;
        sd += t * t;
        u = g_edges[1][2 * e]; v = g_edges[1][2 * e + 1];
        o = (size_t)u * NPTS + v;
        t = g_ddist[o] * invmax - g_ldist[o] * invln;
        sl += t * t;
    }
#pragma unroll
    for (int off = 16; off; off >>= 1) {
        sd += __shfl_down_sync(0xffffffffu, sd, off);
        sl += __shfl_down_sync(0xffffffffu, sl, off);
    }
    __shared__ float ssd[32], ssl[32];
    if ((tid & 31) == 0) { ssd[tid >> 5] = sd; ssl[tid >> 5] = sl; }
    __syncthreads();
    if (tid < 32) {
        sd = ssd[tid]; sl = ssl[tid];
#pragma unroll
        for (int off = 16; off; off >>= 1) {
            sd += __shfl_down_sync(0xffffffffu, sd, off);
            sl += __shfl_down_sync(0xffffffffu, sl, off);
        }
        if (tid == 0) g_topo = (sd + sl) * (1.0f / NEDGE);
    }
}

__global__ void final_kernel(float* __restrict__ out) {
    int i = blockIdx.x * blockDim.x + threadIdx.x;
    if (i < NPTS) out[i] = g_ae[i] + 0.5f * g_topo;
}

extern "C" void kernel_launch(void* const* d_in, const int* in_sizes, int n_in,
                              void* d_out, int out_size) {
    const float* y_true      = (const float*)d_in[0];
    const float* latent      = (const float*)d_in[1];
    const float* y_pred      = (const float*)d_in[2];
    const float* latent_norm = (const float*)d_in[3];
    float* out = (float*)d_out;

    init_kernel<<<16, 256>>>();
    ae_sq_kernel<<<NPTS, 256>>>(y_true, y_pred);
    sq_lat_kernel<<<NPTS, 32>>>(latent);
    dim3 grid(32, 32);
    gram_kernel<<<grid, 256>>>(y_true, DDATA, 0);
    gram_kernel<<<grid, 256>>>(latent, DLAT, 1);
    for (int r = 0; r < ROUNDS; r++) {
        boruvka_scan<<<dim3(512, 2), 256>>>();
        boruvka_merge<<<2, 1024>>>();
    }
    topo_kernel<<<1, 1024>>>(latent_norm);
    final_kernel<<<16, 256>>>(out);
}